// round 16
// baseline (speedup 1.0000x reference)
#include <cuda_runtime.h>
#include <cuda_fp16.h>
#include <math.h>
#include <stdint.h>

// ---------------- problem constants ----------------
#define BSZ    2
#define LEN    2048
#define DIM    768
#define HDIM   1536
#define DSTATE 16
#define ROWS   (BSZ*LEN)   // 4096
#define NCH    (BSZ*HDIM)  // 3072

#define OUT0_OFF 0
#define OUT1_OFF ((size_t)ROWS*DIM)
#define OUT2_OFF (OUT1_OFF + (size_t)ROWS*HDIM*DSTATE)

// ---------------- scratch ----------------
__device__ float  g_apre[ROWS * HDIM];
__device__ float  g_g   [ROWS * HDIM];
__device__ float  g_a   [ROWS * HDIM];
__device__ __half g_aat [ROWS * HDIM];
__device__ __half g_agt [ROWS * HDIM];
__device__ float  g_dl  [ROWS * HDIM];
__device__ float  g_bm  [ROWS * DSTATE];
__device__ __half g_xt  [ROWS * DIM];
__device__ __half g_w1t [HDIM * DIM];
__device__ __half g_w2t [HDIM * DIM];
__device__ __half g_wdt [HDIM * HDIM];
__device__ __half g_wft [DIM * HDIM];

// ---------------- PTX helpers ----------------
__device__ __forceinline__ uint32_t smem_u32(const void* p) {
    uint32_t a;
    asm("{ .reg .u64 t; cvta.to.shared.u64 t, %1; cvt.u32.u64 %0, t; }"
        : "=r"(a) : "l"(p));
    return a;
}
#define CP_ASYNC16(dst, src) \
    asm volatile("cp.async.cg.shared.global [%0], [%1], 16;" :: "r"(dst), "l"(src) : "memory")
#define CP_COMMIT()  asm volatile("cp.async.commit_group;" ::: "memory")
#define CP_WAIT3()   asm volatile("cp.async.wait_group 3;" ::: "memory")

__device__ __forceinline__ void mma_f16(float* c, const uint32_t* a, const uint32_t* b) {
    asm volatile(
        "mma.sync.aligned.m16n8k16.row.col.f32.f16.f16.f32 "
        "{%0,%1,%2,%3}, {%4,%5,%6,%7}, {%8,%9}, {%0,%1,%2,%3};"
        : "+f"(c[0]), "+f"(c[1]), "+f"(c[2]), "+f"(c[3])
        : "r"(a[0]), "r"(a[1]), "r"(a[2]), "r"(a[3]), "r"(b[0]), "r"(b[1]));
}

// ---------------- x -> fp16 ----------------
__global__ void __launch_bounds__(256) convert_x_kernel(
    const float4* __restrict__ x, __half2* __restrict__ xt)
{
    const int i = blockIdx.x * 256 + threadIdx.x;
    float4 v = x[i];
    xt[2 * i]     = __floats2half2_rn(v.x, v.y);
    xt[2 * i + 1] = __floats2half2_rn(v.z, v.w);
}

// ---------------- weights: transpose [K][N] -> [N][K] + fp16 ----------------
__global__ void __launch_bounds__(256) transpose_w_kernel(
    const float* __restrict__ w1, const float* __restrict__ w2,
    const float* __restrict__ wd, const float* __restrict__ wf,
    __half* __restrict__ o1, __half* __restrict__ o2,
    __half* __restrict__ od, __half* __restrict__ of)
{
    __shared__ float tile[32][33];
    const int z = blockIdx.z;
    const float* src; __half* dst; int K, N;
    if      (z == 0) { src = w1; dst = o1; K = DIM;  N = HDIM; }
    else if (z == 1) { src = w2; dst = o2; K = DIM;  N = HDIM; }
    else if (z == 2) { src = wd; dst = od; K = HDIM; N = HDIM; }
    else             { src = wf; dst = of; K = HDIM; N = DIM;  }
    const int kb = blockIdx.y * 32, nb = blockIdx.x * 32;
    if (kb >= K || nb >= N) return;
    const int tx = threadIdx.x & 31, ty = threadIdx.x >> 5;
    #pragma unroll
    for (int i = 0; i < 4; i++)
        tile[ty + 8 * i][tx] = src[(size_t)(kb + ty + 8 * i) * N + nb + tx];
    __syncthreads();
    #pragma unroll
    for (int i = 0; i < 4; i++)
        dst[(size_t)(nb + ty + 8 * i) * K + kb + tx] =
            __float2half_rn(tile[tx][ty + 8 * i]);
}

// ---------------- fp16 tensor-core GEMM body (4-stage pipeline) -------------
#define BKH 32
#define HSTRIDE 40
#define STAGE_BYTES (2 * 128 * HSTRIDE * 2)       // 20480
#define NSTAGE 4
#define GEMM_SMEM_BYTES (NSTAGE * STAGE_BYTES)    // 81920

__device__ __forceinline__ void gemm_body(
    const __half* __restrict__ A, const __half* __restrict__ B,
    const float* __restrict__ bias, const float* __restrict__ bias2,
    float* __restrict__ C, int N, int K, int mode,
    char* smem, int bm, int bn)
{
    const uint32_t smem_b = smem_u32(smem);
    const int tid = threadIdx.x;
    const int wid = tid >> 5, lane = tid & 31;
    const int wm = wid >> 1, wn = wid & 1;
    const int g = lane >> 2, t = lane & 3;

    auto load_tile = [&](int t0, int s) {
        const int k0 = t0 * BKH;
        const uint32_t abase = smem_b + (uint32_t)s * STAGE_BYTES;
        const uint32_t bbase = abase + 128 * HSTRIDE * 2;
        #pragma unroll
        for (int i = 0; i < 4; i++) {
            int idx = i * 128 + tid;
            int r = idx >> 2, c8 = idx & 3;
            CP_ASYNC16(abase + (uint32_t)(r * (HSTRIDE * 2) + c8 * 16),
                       A + (size_t)(bm + r) * K + k0 + c8 * 8);
        }
        #pragma unroll
        for (int i = 0; i < 4; i++) {
            int idx = i * 128 + tid;
            int n = idx >> 2, c8 = idx & 3;
            CP_ASYNC16(bbase + (uint32_t)(n * (HSTRIDE * 2) + c8 * 16),
                       B + (size_t)(bn + n) * K + k0 + c8 * 8);
        }
    };

    float acc[4][8][4];
    #pragma unroll
    for (int mi = 0; mi < 4; mi++)
        #pragma unroll
        for (int nj = 0; nj < 8; nj++)
            #pragma unroll
            for (int q = 0; q < 4; q++) acc[mi][nj][q] = 0.f;

    const int T = K / BKH;
    load_tile(0, 0); CP_COMMIT();
    load_tile(1, 1); CP_COMMIT();
    load_tile(2, 2); CP_COMMIT();

    int s_cur = 0, s_nxt = 3;
    for (int tt = 0; tt < T; tt++) {
        if (tt + 3 < T) load_tile(tt + 3, s_nxt);
        CP_COMMIT();
        CP_WAIT3();
        __syncthreads();

        const uint32_t* Sw = (const uint32_t*)(smem + s_cur * STAGE_BYTES);
        const uint32_t* Aw = Sw;
        const uint32_t* Bw = Sw + 128 * (HSTRIDE / 2);

        #pragma unroll
        for (int kk = 0; kk < 2; kk++) {
            uint32_t af[4][4];
            #pragma unroll
            for (int mi = 0; mi < 4; mi++) {
                const int row = wm * 64 + mi * 16 + g;
                const uint32_t* ap = Aw + row * (HSTRIDE / 2) + kk * 8 + t;
                af[mi][0] = ap[0];
                af[mi][1] = ap[8 * (HSTRIDE / 2)];
                af[mi][2] = ap[4];
                af[mi][3] = ap[8 * (HSTRIDE / 2) + 4];
            }
            uint32_t bf[8][2];
            #pragma unroll
            for (int nj = 0; nj < 8; nj++) {
                const int n = wn * 64 + nj * 8 + g;
                const uint32_t* bp = Bw + n * (HSTRIDE / 2) + kk * 8 + t;
                bf[nj][0] = bp[0];
                bf[nj][1] = bp[4];
            }
            #pragma unroll
            for (int mi = 0; mi < 4; mi++)
                #pragma unroll
                for (int nj = 0; nj < 8; nj++)
                    mma_f16(acc[mi][nj], af[mi], bf[nj]);
        }
        __syncthreads();
        s_cur = (s_cur + 1) & 3;
        s_nxt = (s_nxt + 1) & 3;
    }

    // epilogue
    #pragma unroll
    for (int nj = 0; nj < 8; nj++) {
        const int col = bn + wn * 64 + nj * 8 + t * 2;
        const float bz0 = __ldg(bias + col), bz1 = __ldg(bias + col + 1);
        const float e0 = (mode == 2) ? __ldg(bias2 + col) : 0.f;
        const float e1 = (mode == 2) ? __ldg(bias2 + col + 1) : 0.f;
        #pragma unroll
        for (int mi = 0; mi < 4; mi++) {
            const int row0 = bm + wm * 64 + mi * 16 + g;
            float v[4];
            v[0] = acc[mi][nj][0] + bz0 + e0;
            v[1] = acc[mi][nj][1] + bz1 + e1;
            v[2] = acc[mi][nj][2] + bz0 + e0;
            v[3] = acc[mi][nj][3] + bz1 + e1;
            #pragma unroll
            for (int q = 0; q < 4; q++) {
                if (mode == 1) v[q] = v[q] / (1.f + expf(-v[q]));
                if (mode == 2) v[q] = fmaxf(v[q], 0.f) + log1pf(expf(-fabsf(v[q])));
            }
            *(float2*)(C + (size_t)row0 * N + col)       = make_float2(v[0], v[1]);
            *(float2*)(C + (size_t)(row0 + 8) * N + col) = make_float2(v[2], v[3]);
        }
    }
}

// ---------------- wb body (128 threads, 16 rows/block) ----------------------
__device__ __forceinline__ void wb_body(
    const float* __restrict__ a, const float* __restrict__ WB,
    const float* __restrict__ bB, float* __restrict__ Bm, int base)
{
    const int tid = threadIdx.x;
    const int w = tid >> 5, lane = tid & 31;
    const int r2 = lane >> 4, s = lane & 15;
    const int row0 = base + w * 4 + r2 * 2;

    const float* ar0 = a + (size_t)row0 * HDIM;
    const float* ar1 = ar0 + HDIM;
    float acc0 = 0.f, acc1 = 0.f;
    #pragma unroll 4
    for (int k = 0; k < HDIM; k += 4) {
        float4 a0 = __ldg((const float4*)(ar0 + k));
        float4 a1 = __ldg((const float4*)(ar1 + k));
        float w0 = __ldg(WB + (size_t)(k + 0) * 16 + s);
        float w1 = __ldg(WB + (size_t)(k + 1) * 16 + s);
        float w2 = __ldg(WB + (size_t)(k + 2) * 16 + s);
        float w3 = __ldg(WB + (size_t)(k + 3) * 16 + s);
        acc0 = fmaf(a0.x, w0, acc0); acc0 = fmaf(a0.y, w1, acc0);
        acc0 = fmaf(a0.z, w2, acc0); acc0 = fmaf(a0.w, w3, acc0);
        acc1 = fmaf(a1.x, w0, acc1); acc1 = fmaf(a1.y, w1, acc1);
        acc1 = fmaf(a1.z, w2, acc1); acc1 = fmaf(a1.w, w3, acc1);
    }
    const float bz = __ldg(bB + s);
    Bm[(row0 + 0) * 16 + s] = acc0 + bz;
    Bm[(row0 + 1) * 16 + s] = acc1 + bz;
}

// dual launch: z=0 -> C1; z=1 -> C2 (N2=0 disables); z=2 -> wb slice
__global__ void __launch_bounds__(128, 2) tc_gemm_dual(
    const __half* __restrict__ A1, const __half* __restrict__ B1,
    const float* __restrict__ bias1, const float* __restrict__ biasx1,
    float* __restrict__ C1, int N1, int m1,
    const __half* __restrict__ A2, const __half* __restrict__ B2,
    const float* __restrict__ bias2, const float* __restrict__ biasx2,
    float* __restrict__ C2, int N2, int m2,
    int K,
    const float* __restrict__ wb_a, const float* __restrict__ WB,
    const float* __restrict__ bB, float* __restrict__ Bm)
{
    extern __shared__ char smem[];
    if (blockIdx.z == 0) {
        gemm_body(A1, B1, bias1, biasx1, C1, N1, K, m1, smem,
                  blockIdx.y * 128, blockIdx.x * 128);
    } else if (blockIdx.z == 1) {
        if ((int)blockIdx.x * 128 >= N2) return;
        gemm_body(A2, B2, bias2, biasx2, C2, N2, K, m2, smem,
                  blockIdx.y * 128, blockIdx.x * 128);
    } else {
        if (wb_a == nullptr) return;
        const int bid = blockIdx.y * gridDim.x + blockIdx.x;
        if (bid >= ROWS / 16) return;
        wb_body(wb_a, WB, bB, Bm, bid * 16);
    }
}

// ---------------- scan body (128 threads: 8 channels x 16 states) -----------
// smem tiles [8 l x 8 d] for delta/a, double buffered (in dynamic smem).
__device__ __forceinline__ void scan_body(
    const float* __restrict__ delta, const float* __restrict__ a,
    const float* __restrict__ Bm, const float* __restrict__ A,
    float* __restrict__ hid, char* smem, int bid)
{
    float (*sd)[8][8] = (float(*)[8][8])(smem);         // [2][8][8]
    float (*sa)[8][8] = (float(*)[8][8])(smem + 512);

    const int tid = threadIdx.x;
    const int ch = tid >> 4;            // 0..7
    const int s  = tid & 15;
    const int g0 = bid * 8;
    const int b  = g0 / HDIM;
    const int d0 = g0 % HDIM;
    const int d  = d0 + ch;

    const int which = tid >> 6;         // 0: delta, 1: a
    const int li = (tid >> 3) & 7;
    const int di = tid & 7;
    const float* lsrc = (which ? a : delta)
                        + (size_t)b * LEN * HDIM + d0 + di;

    const float Ae = expf(-A[d * DSTATE + s]);
    float h = 0.f;

    const float* bptr = Bm + (size_t)b * LEN * DSTATE + s;
    float* hptr = hid + ((size_t)b * LEN * HDIM + d) * DSTATE + s;

    {   // prologue: chunk 0 -> buffer 0
        float v = lsrc[(size_t)li * HDIM];
        if (which) sa[0][li][di] = v; else sd[0][li][di] = v;
    }

    for (int c = 0; c < LEN / 8; c++) {
        __syncthreads();
        if (c + 1 < LEN / 8) {
            float v = lsrc[(size_t)((c + 1) * 8 + li) * HDIM];
            if (which) sa[(c + 1) & 1][li][di] = v;
            else       sd[(c + 1) & 1][li][di] = v;
        }
        const int l0 = c * 8;
        const int buf = c & 1;
        float bv[8];
        #pragma unroll
        for (int u = 0; u < 8; u++)
            bv[u] = __ldg(bptr + (size_t)(l0 + u) * DSTATE);
        #pragma unroll
        for (int u = 0; u < 8; u++) {
            const float dv = sd[buf][u][ch];
            const float av = sa[buf][u][ch];
            h = fmaf(Ae * dv, h, bv[u] * dv * av);
            __stcs(hptr + (size_t)(l0 + u) * (HDIM * DSTATE), h);
        }
    }
}

// scan ∥ Wf gemm: z=0 -> Wf gemm (x < N/128 active); z=1 -> scan slice
__global__ void __launch_bounds__(128, 2) scan_wf_kernel(
    const __half* __restrict__ Ag, const __half* __restrict__ Bg,
    const float* __restrict__ biasg, float* __restrict__ Cg, int Ng, int Kg,
    const float* __restrict__ delta, const float* __restrict__ a,
    const float* __restrict__ Bm, const float* __restrict__ A,
    float* __restrict__ hid)
{
    extern __shared__ char smem[];
    if (blockIdx.z == 0) {
        if ((int)blockIdx.x * 128 >= Ng) return;
        gemm_body(Ag, Bg, biasg, nullptr, Cg, Ng, Kg, 0, smem,
                  blockIdx.y * 128, blockIdx.x * 128);
    } else {
        const int bid = blockIdx.y * gridDim.x + blockIdx.x;   // 0..383
        scan_body(delta, a, Bm, A, hid, smem, bid);
    }
}

// ---------------- conv(K=4)+silu, float4 over d ------------------------------
__global__ void __launch_bounds__(256) conv_fuse_kernel(
    const float* __restrict__ apre, const float4* __restrict__ cw4,
    const float4* __restrict__ cb4, const float4* __restrict__ g4,
    float4* __restrict__ aa4, __half2* __restrict__ aat2,
    __half2* __restrict__ agt2, float* __restrict__ out2)
{
    const int i = blockIdx.x * 256 + threadIdx.x;
    const int d4 = i % (HDIM / 4);
    const int r  = i / (HDIM / 4);
    const int l  = r & (LEN - 1);
    const int d  = d4 * 4;

    const float4 w0 = __ldg(cw4 + d + 0);
    const float4 w1 = __ldg(cw4 + d + 1);
    const float4 w2 = __ldg(cw4 + d + 2);
    const float4 w3 = __ldg(cw4 + d + 3);
    float4 s = __ldg(cb4 + d4);

    #pragma unroll
    for (int j = 0; j < 4; j++) {
        const int ll = l - 3 + j;
        if (ll >= 0) {
            const float4 ap = __ldg((const float4*)apre + (size_t)(r - 3 + j) * (HDIM / 4) + d4);
            const float wj0 = (&w0.x)[j], wj1 = (&w1.x)[j],
                        wj2 = (&w2.x)[j], wj3 = (&w3.x)[j];
            s.x = fmaf(ap.x, wj0, s.x);
            s.y = fmaf(ap.y, wj1, s.y);
            s.z = fmaf(ap.z, wj2, s.z);
            s.w = fmaf(ap.w, wj3, s.w);
        }
    }
    float4 a;
    a.x = s.x / (1.f + expf(-s.x));
    a.y = s.y / (1.f + expf(-s.y));
    a.z = s.z / (1.f + expf(-s.z));
    a.w = s.w / (1.f + expf(-s.w));

    aa4[i] = a;
    aat2[2 * i]     = __floats2half2_rn(a.x, a.y);
    aat2[2 * i + 1] = __floats2half2_rn(a.z, a.w);
    const float4 gv = __ldg(g4 + i);
    agt2[2 * i]     = __floats2half2_rn(a.x * gv.x, a.y * gv.y);
    agt2[2 * i + 1] = __floats2half2_rn(a.z * gv.z, a.w * gv.w);

    float* o = out2 + (size_t)r * (HDIM - 1) + d;
    if (d >= 1) o[-1] = a.x;
    o[0] = a.y; o[1] = a.z;
    if (d + 3 < HDIM) o[2] = a.w;
}

// ---------------------------------------------------------------------------
extern "C" void kernel_launch(void* const* d_in, const int* in_sizes, int n_in,
                              void* d_out, int out_size)
{
    const float* x  = (const float*)d_in[0];
    const float* W1 = (const float*)d_in[1];
    const float* b1 = (const float*)d_in[2];
    const float* W2 = (const float*)d_in[3];
    const float* b2 = (const float*)d_in[4];
    const float* cw = (const float*)d_in[5];
    const float* cb = (const float*)d_in[6];
    const float* Wf = (const float*)d_in[7];
    const float* bf = (const float*)d_in[8];
    const float* A  = (const float*)d_in[9];
    const float* WB = (const float*)d_in[10];
    const float* bB = (const float*)d_in[11];
    const float* WD = (const float*)d_in[14];
    const float* bD = (const float*)d_in[15];
    const float* Dv = (const float*)d_in[16];

    float* out = (float*)d_out;

    float *apre, *gg, *aa, *dl, *bm;
    __half *aat, *agt, *xt, *w1t, *w2t, *wdt, *wft;
    cudaGetSymbolAddress((void**)&apre, g_apre);
    cudaGetSymbolAddress((void**)&gg,   g_g);
    cudaGetSymbolAddress((void**)&aa,   g_a);
    cudaGetSymbolAddress((void**)&aat,  g_aat);
    cudaGetSymbolAddress((void**)&agt,  g_agt);
    cudaGetSymbolAddress((void**)&dl,   g_dl);
    cudaGetSymbolAddress((void**)&bm,   g_bm);
    cudaGetSymbolAddress((void**)&xt,   g_xt);
    cudaGetSymbolAddress((void**)&w1t,  g_w1t);
    cudaGetSymbolAddress((void**)&w2t,  g_w2t);
    cudaGetSymbolAddress((void**)&wdt,  g_wdt);
    cudaGetSymbolAddress((void**)&wft,  g_wft);

    cudaFuncSetAttribute(tc_gemm_dual,  cudaFuncAttributeMaxDynamicSharedMemorySize, GEMM_SMEM_BYTES);
    cudaFuncSetAttribute(scan_wf_kernel, cudaFuncAttributeMaxDynamicSharedMemorySize, GEMM_SMEM_BYTES);

    // 0) x -> fp16; weights -> fp16 transposed [N][K]
    convert_x_kernel<<<(ROWS*DIM/4)/256, 256>>>((const float4*)x, (__half2*)xt);
    transpose_w_kernel<<<dim3(HDIM/32, HDIM/32, 4), 256>>>(
        W1, W2, WD, Wf, w1t, w2t, wdt, wft);

    // 1+2) apre = x@W1+b1 (z=0) ; g = silu(x@W2+b2) (z=1)
    tc_gemm_dual<<<dim3(HDIM/128, ROWS/128, 2), 128, GEMM_SMEM_BYTES>>>(
        xt, w1t, b1, nullptr, apre, HDIM, 0,
        xt, w2t, b2, nullptr, gg,   HDIM, 1,
        DIM,
        nullptr, nullptr, nullptr, nullptr);

    // 3) conv + silu + a*g + slice
    conv_fuse_kernel<<<(ROWS*HDIM/4)/256, 256>>>(
        apre, (const float4*)cw, (const float4*)cb, (const float4*)gg,
        (float4*)aa, (__half2*)aat, (__half2*)agt, out + OUT2_OFF);

    // 4+5) delta gemm (z=0) ∥ wb (z=2); z=1 disabled via N2=0
    tc_gemm_dual<<<dim3(HDIM/128, ROWS/128, 3), 128, GEMM_SMEM_BYTES>>>(
        aat, wdt, bD, Dv,      dl,  HDIM, 2,
        aat, wdt, bD, nullptr, dl,  0,    0,
        HDIM,
        aa, WB, bB, bm);

    // 6+7) Wf gemm (z=0, x<6 active) ∥ smem-staged scan (z=1)
    scan_wf_kernel<<<dim3(12, 32, 2), 128, GEMM_SMEM_BYTES>>>(
        agt, wft, bf, out + OUT0_OFF, DIM, HDIM,
        dl, aa, bm, A, out + OUT1_OFF);
}

// round 17
// speedup vs baseline: 1.2660x; 1.2660x over previous
#include <cuda_runtime.h>
#include <cuda_fp16.h>
#include <math.h>
#include <stdint.h>

// ---------------- problem constants ----------------
#define BSZ    2
#define LEN    2048
#define DIM    768
#define HDIM   1536
#define DSTATE 16
#define ROWS   (BSZ*LEN)   // 4096
#define NCH    (BSZ*HDIM)  // 3072

#define OUT0_OFF 0
#define OUT1_OFF ((size_t)ROWS*DIM)
#define OUT2_OFF (OUT1_OFF + (size_t)ROWS*HDIM*DSTATE)

// ---------------- scratch ----------------
__device__ float  g_apre[ROWS * HDIM];
__device__ float  g_g   [ROWS * HDIM];
__device__ float  g_a   [ROWS * HDIM];
__device__ __half g_aat [ROWS * HDIM];
__device__ __half g_agt [ROWS * HDIM];
__device__ float  g_dl  [ROWS * HDIM];
__device__ float  g_bm  [ROWS * DSTATE];
__device__ __half g_xt  [ROWS * DIM];
__device__ __half g_w1t [HDIM * DIM];
__device__ __half g_w2t [HDIM * DIM];
__device__ __half g_wdt [HDIM * HDIM];
__device__ __half g_wft [DIM * HDIM];

// ---------------- PTX helpers ----------------
__device__ __forceinline__ uint32_t smem_u32(const void* p) {
    uint32_t a;
    asm("{ .reg .u64 t; cvta.to.shared.u64 t, %1; cvt.u32.u64 %0, t; }"
        : "=r"(a) : "l"(p));
    return a;
}
#define CP_ASYNC16(dst, src) \
    asm volatile("cp.async.cg.shared.global [%0], [%1], 16;" :: "r"(dst), "l"(src) : "memory")
#define CP_COMMIT()  asm volatile("cp.async.commit_group;" ::: "memory")
#define CP_WAIT3()   asm volatile("cp.async.wait_group 3;" ::: "memory")

__device__ __forceinline__ void mma_f16(float* c, const uint32_t* a, const uint32_t* b) {
    asm volatile(
        "mma.sync.aligned.m16n8k16.row.col.f32.f16.f16.f32 "
        "{%0,%1,%2,%3}, {%4,%5,%6,%7}, {%8,%9}, {%0,%1,%2,%3};"
        : "+f"(c[0]), "+f"(c[1]), "+f"(c[2]), "+f"(c[3])
        : "r"(a[0]), "r"(a[1]), "r"(a[2]), "r"(a[3]), "r"(b[0]), "r"(b[1]));
}

// ---------------- x -> fp16 ----------------
__global__ void __launch_bounds__(256) convert_x_kernel(
    const float4* __restrict__ x, __half2* __restrict__ xt)
{
    const int i = blockIdx.x * 256 + threadIdx.x;
    float4 v = x[i];
    xt[2 * i]     = __floats2half2_rn(v.x, v.y);
    xt[2 * i + 1] = __floats2half2_rn(v.z, v.w);
}

// ---------------- weights: transpose [K][N] -> [N][K] + fp16 ----------------
__global__ void __launch_bounds__(256) transpose_w_kernel(
    const float* __restrict__ w1, const float* __restrict__ w2,
    const float* __restrict__ wd, const float* __restrict__ wf,
    __half* __restrict__ o1, __half* __restrict__ o2,
    __half* __restrict__ od, __half* __restrict__ of)
{
    __shared__ float tile[32][33];
    const int z = blockIdx.z;
    const float* src; __half* dst; int K, N;
    if      (z == 0) { src = w1; dst = o1; K = DIM;  N = HDIM; }
    else if (z == 1) { src = w2; dst = o2; K = DIM;  N = HDIM; }
    else if (z == 2) { src = wd; dst = od; K = HDIM; N = HDIM; }
    else             { src = wf; dst = of; K = HDIM; N = DIM;  }
    const int kb = blockIdx.y * 32, nb = blockIdx.x * 32;
    if (kb >= K || nb >= N) return;
    const int tx = threadIdx.x & 31, ty = threadIdx.x >> 5;
    #pragma unroll
    for (int i = 0; i < 4; i++)
        tile[ty + 8 * i][tx] = src[(size_t)(kb + ty + 8 * i) * N + nb + tx];
    __syncthreads();
    #pragma unroll
    for (int i = 0; i < 4; i++)
        dst[(size_t)(nb + ty + 8 * i) * K + kb + tx] =
            __float2half_rn(tile[tx][ty + 8 * i]);
}

// ---------------- fp16 tensor-core GEMM body (4-stage pipeline) -------------
#define BKH 32
#define HSTRIDE 40
#define STAGE_BYTES (2 * 128 * HSTRIDE * 2)       // 20480
#define NSTAGE 4
#define GEMM_SMEM_BYTES (NSTAGE * STAGE_BYTES)    // 81920

__device__ __forceinline__ void gemm_body(
    const __half* __restrict__ A, const __half* __restrict__ B,
    const float* __restrict__ bias, const float* __restrict__ bias2,
    float* __restrict__ C, int N, int K, int mode,
    char* smem, int bm, int bn)
{
    const uint32_t smem_b = smem_u32(smem);
    const int tid = threadIdx.x;
    const int wid = tid >> 5, lane = tid & 31;
    const int wm = wid >> 1, wn = wid & 1;
    const int g = lane >> 2, t = lane & 3;

    auto load_tile = [&](int t0, int s) {
        const int k0 = t0 * BKH;
        const uint32_t abase = smem_b + (uint32_t)s * STAGE_BYTES;
        const uint32_t bbase = abase + 128 * HSTRIDE * 2;
        #pragma unroll
        for (int i = 0; i < 4; i++) {
            int idx = i * 128 + tid;
            int r = idx >> 2, c8 = idx & 3;
            CP_ASYNC16(abase + (uint32_t)(r * (HSTRIDE * 2) + c8 * 16),
                       A + (size_t)(bm + r) * K + k0 + c8 * 8);
        }
        #pragma unroll
        for (int i = 0; i < 4; i++) {
            int idx = i * 128 + tid;
            int n = idx >> 2, c8 = idx & 3;
            CP_ASYNC16(bbase + (uint32_t)(n * (HSTRIDE * 2) + c8 * 16),
                       B + (size_t)(bn + n) * K + k0 + c8 * 8);
        }
    };

    float acc[4][8][4];
    #pragma unroll
    for (int mi = 0; mi < 4; mi++)
        #pragma unroll
        for (int nj = 0; nj < 8; nj++)
            #pragma unroll
            for (int q = 0; q < 4; q++) acc[mi][nj][q] = 0.f;

    const int T = K / BKH;
    load_tile(0, 0); CP_COMMIT();
    load_tile(1, 1); CP_COMMIT();
    load_tile(2, 2); CP_COMMIT();

    int s_cur = 0, s_nxt = 3;
    for (int tt = 0; tt < T; tt++) {
        if (tt + 3 < T) load_tile(tt + 3, s_nxt);
        CP_COMMIT();
        CP_WAIT3();
        __syncthreads();

        const uint32_t* Sw = (const uint32_t*)(smem + s_cur * STAGE_BYTES);
        const uint32_t* Aw = Sw;
        const uint32_t* Bw = Sw + 128 * (HSTRIDE / 2);

        #pragma unroll
        for (int kk = 0; kk < 2; kk++) {
            uint32_t af[4][4];
            #pragma unroll
            for (int mi = 0; mi < 4; mi++) {
                const int row = wm * 64 + mi * 16 + g;
                const uint32_t* ap = Aw + row * (HSTRIDE / 2) + kk * 8 + t;
                af[mi][0] = ap[0];
                af[mi][1] = ap[8 * (HSTRIDE / 2)];
                af[mi][2] = ap[4];
                af[mi][3] = ap[8 * (HSTRIDE / 2) + 4];
            }
            uint32_t bf[8][2];
            #pragma unroll
            for (int nj = 0; nj < 8; nj++) {
                const int n = wn * 64 + nj * 8 + g;
                const uint32_t* bp = Bw + n * (HSTRIDE / 2) + kk * 8 + t;
                bf[nj][0] = bp[0];
                bf[nj][1] = bp[4];
            }
            #pragma unroll
            for (int mi = 0; mi < 4; mi++)
                #pragma unroll
                for (int nj = 0; nj < 8; nj++)
                    mma_f16(acc[mi][nj], af[mi], bf[nj]);
        }
        __syncthreads();
        s_cur = (s_cur + 1) & 3;
        s_nxt = (s_nxt + 1) & 3;
    }

    // epilogue
    #pragma unroll
    for (int nj = 0; nj < 8; nj++) {
        const int col = bn + wn * 64 + nj * 8 + t * 2;
        const float bz0 = __ldg(bias + col), bz1 = __ldg(bias + col + 1);
        const float e0 = (mode == 2) ? __ldg(bias2 + col) : 0.f;
        const float e1 = (mode == 2) ? __ldg(bias2 + col + 1) : 0.f;
        #pragma unroll
        for (int mi = 0; mi < 4; mi++) {
            const int row0 = bm + wm * 64 + mi * 16 + g;
            float v[4];
            v[0] = acc[mi][nj][0] + bz0 + e0;
            v[1] = acc[mi][nj][1] + bz1 + e1;
            v[2] = acc[mi][nj][2] + bz0 + e0;
            v[3] = acc[mi][nj][3] + bz1 + e1;
            #pragma unroll
            for (int q = 0; q < 4; q++) {
                if (mode == 1) v[q] = v[q] / (1.f + expf(-v[q]));
                if (mode == 2) v[q] = fmaxf(v[q], 0.f) + log1pf(expf(-fabsf(v[q])));
            }
            *(float2*)(C + (size_t)row0 * N + col)       = make_float2(v[0], v[1]);
            *(float2*)(C + (size_t)(row0 + 8) * N + col) = make_float2(v[2], v[3]);
        }
    }
}

// ---------------- wb body (128 threads, 16 rows/block) ----------------------
__device__ __forceinline__ void wb_body(
    const float* __restrict__ a, const float* __restrict__ WB,
    const float* __restrict__ bB, float* __restrict__ Bm, int base)
{
    const int tid = threadIdx.x;
    const int w = tid >> 5, lane = tid & 31;
    const int r2 = lane >> 4, s = lane & 15;
    const int row0 = base + w * 4 + r2 * 2;

    const float* ar0 = a + (size_t)row0 * HDIM;
    const float* ar1 = ar0 + HDIM;
    float acc0 = 0.f, acc1 = 0.f;
    #pragma unroll 4
    for (int k = 0; k < HDIM; k += 4) {
        float4 a0 = __ldg((const float4*)(ar0 + k));
        float4 a1 = __ldg((const float4*)(ar1 + k));
        float w0 = __ldg(WB + (size_t)(k + 0) * 16 + s);
        float w1 = __ldg(WB + (size_t)(k + 1) * 16 + s);
        float w2 = __ldg(WB + (size_t)(k + 2) * 16 + s);
        float w3 = __ldg(WB + (size_t)(k + 3) * 16 + s);
        acc0 = fmaf(a0.x, w0, acc0); acc0 = fmaf(a0.y, w1, acc0);
        acc0 = fmaf(a0.z, w2, acc0); acc0 = fmaf(a0.w, w3, acc0);
        acc1 = fmaf(a1.x, w0, acc1); acc1 = fmaf(a1.y, w1, acc1);
        acc1 = fmaf(a1.z, w2, acc1); acc1 = fmaf(a1.w, w3, acc1);
    }
    const float bz = __ldg(bB + s);
    Bm[(row0 + 0) * 16 + s] = acc0 + bz;
    Bm[(row0 + 1) * 16 + s] = acc1 + bz;
}

// dual launch: z=0 -> C1; z=1 -> C2 (extra blocks exit); z=2 -> wb slice
__global__ void __launch_bounds__(128, 2) tc_gemm_dual(
    const __half* __restrict__ A1, const __half* __restrict__ B1,
    const float* __restrict__ bias1, const float* __restrict__ biasx1,
    float* __restrict__ C1, int N1, int m1,
    const __half* __restrict__ A2, const __half* __restrict__ B2,
    const float* __restrict__ bias2, const float* __restrict__ biasx2,
    float* __restrict__ C2, int N2, int m2,
    int K,
    const float* __restrict__ wb_a, const float* __restrict__ WB,
    const float* __restrict__ bB, float* __restrict__ Bm)
{
    extern __shared__ char smem[];
    if (blockIdx.z == 0) {
        gemm_body(A1, B1, bias1, biasx1, C1, N1, K, m1, smem,
                  blockIdx.y * 128, blockIdx.x * 128);
    } else if (blockIdx.z == 1) {
        if ((int)blockIdx.x * 128 >= N2) return;
        gemm_body(A2, B2, bias2, biasx2, C2, N2, K, m2, smem,
                  blockIdx.y * 128, blockIdx.x * 128);
    } else {
        if (wb_a == nullptr) return;
        const int bid = blockIdx.y * gridDim.x + blockIdx.x;
        if (bid >= ROWS / 16) return;
        wb_body(wb_a, WB, bB, Bm, bid * 16);
    }
}

// ---------------- conv(K=4)+silu, float4 over d ------------------------------
__global__ void __launch_bounds__(256) conv_fuse_kernel(
    const float* __restrict__ apre, const float4* __restrict__ cw4,
    const float4* __restrict__ cb4, const float4* __restrict__ g4,
    float4* __restrict__ aa4, __half2* __restrict__ aat2,
    __half2* __restrict__ agt2, float* __restrict__ out2)
{
    const int i = blockIdx.x * 256 + threadIdx.x;
    const int d4 = i % (HDIM / 4);
    const int r  = i / (HDIM / 4);
    const int l  = r & (LEN - 1);
    const int d  = d4 * 4;

    const float4 w0 = __ldg(cw4 + d + 0);
    const float4 w1 = __ldg(cw4 + d + 1);
    const float4 w2 = __ldg(cw4 + d + 2);
    const float4 w3 = __ldg(cw4 + d + 3);
    float4 s = __ldg(cb4 + d4);

    #pragma unroll
    for (int j = 0; j < 4; j++) {
        const int ll = l - 3 + j;
        if (ll >= 0) {
            const float4 ap = __ldg((const float4*)apre + (size_t)(r - 3 + j) * (HDIM / 4) + d4);
            const float wj0 = (&w0.x)[j], wj1 = (&w1.x)[j],
                        wj2 = (&w2.x)[j], wj3 = (&w3.x)[j];
            s.x = fmaf(ap.x, wj0, s.x);
            s.y = fmaf(ap.y, wj1, s.y);
            s.z = fmaf(ap.z, wj2, s.z);
            s.w = fmaf(ap.w, wj3, s.w);
        }
    }
    float4 a;
    a.x = s.x / (1.f + expf(-s.x));
    a.y = s.y / (1.f + expf(-s.y));
    a.z = s.z / (1.f + expf(-s.z));
    a.w = s.w / (1.f + expf(-s.w));

    aa4[i] = a;
    aat2[2 * i]     = __floats2half2_rn(a.x, a.y);
    aat2[2 * i + 1] = __floats2half2_rn(a.z, a.w);
    const float4 gv = __ldg(g4 + i);
    agt2[2 * i]     = __floats2half2_rn(a.x * gv.x, a.y * gv.y);
    agt2[2 * i + 1] = __floats2half2_rn(a.z * gv.z, a.w * gv.w);

    float* o = out2 + (size_t)r * (HDIM - 1) + d;
    if (d >= 1) o[-1] = a.x;
    o[0] = a.y; o[1] = a.z;
    if (d + 3 < HDIM) o[2] = a.w;
}

// ---------------- fused selective scan -> hid (smem-staged dv/av/bv) --------
// Block = 256 thr = 16 channels (same b) x 16 states.
// delta/a tiles [8 l x 16 d] + Bm tile [8 l x 16 s] cooperatively loaded.
__global__ void __launch_bounds__(256) scan_kernel(
    const float* __restrict__ delta, const float* __restrict__ a,
    const float* __restrict__ Bm, const float* __restrict__ A,
    float* __restrict__ hid)
{
    __shared__ float sd[2][8][16];
    __shared__ float sa[2][8][16];
    __shared__ float sb[2][8][16];

    const int tid = threadIdx.x;
    const int ch = tid >> 4;            // channel within block 0..15
    const int s  = tid & 15;            // state
    const int g0 = blockIdx.x * 16;
    const int b  = g0 / HDIM;
    const int d0 = g0 % HDIM;
    const int d  = d0 + ch;

    // loader roles: threads 0-127 load delta, 128-255 load a;
    // threads 0-127 ALSO load the Bm tile (8l x 16s, 64B-coalesced rows).
    const int which = tid >> 7;
    const int li = (tid >> 4) & 7;
    const int di = tid & 15;
    const float* lsrc = (which ? a : delta)
                        + (size_t)b * LEN * HDIM + d0 + di;
    const float* bsrc = Bm + ((size_t)b * LEN + li) * DSTATE + di;

    const float Ae = expf(-A[d * DSTATE + s]);
    float h = 0.f;

    float* hptr = hid + ((size_t)b * LEN * HDIM + d) * DSTATE + s;

    // prologue: chunk 0 -> buffer 0
    {
        float v = lsrc[(size_t)li * HDIM];
        if (which) sa[0][li][di] = v;
        else {
            sd[0][li][di] = v;
            sb[0][li][di] = bsrc[0];
        }
    }

    for (int c = 0; c < LEN / 8; c++) {
        __syncthreads();
        if (c + 1 < LEN / 8) {
            float v = lsrc[(size_t)((c + 1) * 8 + li) * HDIM];
            const int nb = (c + 1) & 1;
            if (which) sa[nb][li][di] = v;
            else {
                sd[nb][li][di] = v;
                sb[nb][li][di] = bsrc[(size_t)(c + 1) * 8 * DSTATE];
            }
        }
        const int l0 = c * 8;
        const int buf = c & 1;
        #pragma unroll
        for (int u = 0; u < 8; u++) {
            const float dv = sd[buf][u][ch];
            const float av = sa[buf][u][ch];
            const float bv = sb[buf][u][s];
            h = fmaf(Ae * dv, h, bv * dv * av);
            __stcs(hptr + (size_t)(l0 + u) * (HDIM * DSTATE), h);
        }
    }
}

// ---------------------------------------------------------------------------
extern "C" void kernel_launch(void* const* d_in, const int* in_sizes, int n_in,
                              void* d_out, int out_size)
{
    const float* x  = (const float*)d_in[0];
    const float* W1 = (const float*)d_in[1];
    const float* b1 = (const float*)d_in[2];
    const float* W2 = (const float*)d_in[3];
    const float* b2 = (const float*)d_in[4];
    const float* cw = (const float*)d_in[5];
    const float* cb = (const float*)d_in[6];
    const float* Wf = (const float*)d_in[7];
    const float* bf = (const float*)d_in[8];
    const float* A  = (const float*)d_in[9];
    const float* WB = (const float*)d_in[10];
    const float* bB = (const float*)d_in[11];
    const float* WD = (const float*)d_in[14];
    const float* bD = (const float*)d_in[15];
    const float* Dv = (const float*)d_in[16];

    float* out = (float*)d_out;

    float *apre, *gg, *aa, *dl, *bm;
    __half *aat, *agt, *xt, *w1t, *w2t, *wdt, *wft;
    cudaGetSymbolAddress((void**)&apre, g_apre);
    cudaGetSymbolAddress((void**)&gg,   g_g);
    cudaGetSymbolAddress((void**)&aa,   g_a);
    cudaGetSymbolAddress((void**)&aat,  g_aat);
    cudaGetSymbolAddress((void**)&agt,  g_agt);
    cudaGetSymbolAddress((void**)&dl,   g_dl);
    cudaGetSymbolAddress((void**)&bm,   g_bm);
    cudaGetSymbolAddress((void**)&xt,   g_xt);
    cudaGetSymbolAddress((void**)&w1t,  g_w1t);
    cudaGetSymbolAddress((void**)&w2t,  g_w2t);
    cudaGetSymbolAddress((void**)&wdt,  g_wdt);
    cudaGetSymbolAddress((void**)&wft,  g_wft);

    cudaFuncSetAttribute(tc_gemm_dual, cudaFuncAttributeMaxDynamicSharedMemorySize, GEMM_SMEM_BYTES);

    // 0) x -> fp16; weights -> fp16 transposed [N][K]
    convert_x_kernel<<<(ROWS*DIM/4)/256, 256>>>((const float4*)x, (__half2*)xt);
    transpose_w_kernel<<<dim3(HDIM/32, HDIM/32, 4), 256>>>(
        W1, W2, WD, Wf, w1t, w2t, wdt, wft);

    // 1+2) apre = x@W1+b1 (z=0) ; g = silu(x@W2+b2) (z=1)
    tc_gemm_dual<<<dim3(HDIM/128, ROWS/128, 2), 128, GEMM_SMEM_BYTES>>>(
        xt, w1t, b1, nullptr, apre, HDIM, 0,
        xt, w2t, b2, nullptr, gg,   HDIM, 1,
        DIM,
        nullptr, nullptr, nullptr, nullptr);

    // 3) conv + silu + a*g + slice
    conv_fuse_kernel<<<(ROWS*HDIM/4)/256, 256>>>(
        apre, (const float4*)cw, (const float4*)cb, (const float4*)gg,
        (float4*)aa, (__half2*)aat, (__half2*)agt, out + OUT2_OFF);

    // 4+5+6) delta gemm (z=0) ∥ Wf gemm (z=1) ∥ wb (z=2)
    tc_gemm_dual<<<dim3(HDIM/128, ROWS/128, 3), 128, GEMM_SMEM_BYTES>>>(
        aat, wdt, bD, Dv,      dl,              HDIM, 2,
        agt, wft, bf, nullptr, out + OUT0_OFF,  DIM,  0,
        HDIM,
        aa, WB, bB, bm);

    // 7) hid via smem-staged selective scan (16 channels x 16 states / block)
    scan_kernel<<<NCH/16, 256>>>(dl, aa, bm, A, out + OUT1_OFF);
}